// round 8
// baseline (speedup 1.0000x reference)
#include <cuda_runtime.h>
#include <cstdint>

#define BB   4
#define CC   128
#define HW   224
#define PHW  7
#define PP   49
#define ALPHA 0.5f

#define N_OUT 25690112ull
#define N_SCC 67108864ull

// smem layout (floats)
#define FS      60          // F stride
#define LS      132         // L stride
#define FL_OFF  7680        // 128*60
#define L_OFF   15360
#define L_WARP  4224        // 2 * 16*132
#define LLO     2112
#define MU_OFF  49152       // 15360 + 8*4224
#define SMEM_FLOATS 49280

__device__ __forceinline__ float tf32_hi(float x) {
    uint32_t r; asm("cvt.rna.tf32.f32 %0, %1;" : "=r"(r) : "f"(x));
    return __uint_as_float(r);
}
__device__ __forceinline__ void mma8(float* c,
                                     uint32_t a0, uint32_t a1, uint32_t a2, uint32_t a3,
                                     uint32_t b0, uint32_t b1) {
    asm volatile("mma.sync.aligned.m16n8k8.row.col.f32.tf32.tf32.f32 "
        "{%0,%1,%2,%3}, {%4,%5,%6,%7}, {%8,%9}, {%0,%1,%2,%3};"
        : "+f"(c[0]), "+f"(c[1]), "+f"(c[2]), "+f"(c[3])
        : "r"(a0), "r"(a1), "r"(a2), "r"(a3), "r"(b0), "r"(b1));
}

__global__ __launch_bounds__(256, 1)
void bdca_mma_kernel(const float* __restrict__ x, const float* __restrict__ beta,
                     float* __restrict__ out, float* __restrict__ Sc,
                     float* __restrict__ cov, float* __restrict__ ecmap)
{
    extern __shared__ float sm[];
    float* Fh = sm;
    float* Fl = sm + FL_OFF;
    float* mu = sm + MU_OFF;
    const uint32_t* FhU = (const uint32_t*)Fh;
    const uint32_t* FlU = (const uint32_t*)Fl;

    const int tid = threadIdx.x;
    const int w = tid >> 5, l = tid & 31;
    const int g = l >> 2, tg = l & 3;
    float* Lh = sm + L_OFF + w * L_WARP;
    float* Ll = Lh + LLO;

    const int bm = blockIdx.x;
    const int b  = bm >> 10, m = bm & 1023;
    const int hh = m >> 5, ww = m & 31;
    const size_t xoff = (size_t)b * (CC * HW * HW) + (size_t)(hh * PHW) * HW + (size_t)(ww * PHW);

    // ---- zero F pad cols 49..59, stage F hi/lo ----
    for (int t = tid; t < CC * 11; t += 256) {
        int c = t / 11, p = 49 + t % 11;
        Fh[c * FS + p] = 0.f;
        Fl[c * FS + p] = 0.f;
    }
    for (int idx = tid; idx < CC * PP; idx += 256) {
        int c = idx / PP, p = idx - c * PP;
        int i = p / PHW, j = p - i * PHW;
        float xv = __ldg(x + xoff + (size_t)c * (HW * HW) + i * HW + j);
        float hi = tf32_hi(xv);
        Fh[c * FS + p] = hi;
        Fl[c * FS + p] = tf32_hi(xv - hi);
    }
    __syncthreads();

    // ---- mu: warp w owns channels 16w..16w+15, p-parallel + shuffle reduce ----
    {
        #pragma unroll 4
        for (int cc = 0; cc < 16; cc++) {
            int c = 16 * w + cc;
            float v = Fh[c * FS + l] + Fl[c * FS + l];
            if (l < 17) v += Fh[c * FS + 32 + l] + Fl[c * FS + 32 + l];
            #pragma unroll
            for (int o = 16; o; o >>= 1) v += __shfl_xor_sync(0xffffffffu, v, o);
            if (l == 0) mu[c] = v * (1.f / 49.f);
        }
    }
    __syncthreads();

    const int r1 = 16 * w + g;      // row in this warp's strip (and r1+8)

    // ---- GEMM1: G = F * F^T, warp strip 16 rows x 128 cols, split tf32 ----
    float acc[16][4];
    #pragma unroll
    for (int n = 0; n < 16; n++)
        #pragma unroll
        for (int j = 0; j < 4; j++) acc[n][j] = 0.f;

    #pragma unroll 1
    for (int k = 0; k < 7; k++) {
        const int ko = 8 * k + tg;
        uint32_t a0h = FhU[r1 * FS + ko],        a1h = FhU[(r1 + 8) * FS + ko];
        uint32_t a2h = FhU[r1 * FS + ko + 4],    a3h = FhU[(r1 + 8) * FS + ko + 4];
        uint32_t a0l = FlU[r1 * FS + ko],        a1l = FlU[(r1 + 8) * FS + ko];
        uint32_t a2l = FlU[r1 * FS + ko + 4],    a3l = FlU[(r1 + 8) * FS + ko + 4];
        #pragma unroll
        for (int n = 0; n < 16; n++) {
            const int br = (8 * n + g) * FS + ko;
            uint32_t b0h = FhU[br], b1h = FhU[br + 4];
            uint32_t b0l = FlU[br], b1l = FlU[br + 4];
            mma8(acc[n], a0h, a1h, a2h, a3h, b0h, b1h);
            mma8(acc[n], a0h, a1h, a2h, a3h, b0l, b1l);
            mma8(acc[n], a0l, a1l, a2l, a3l, b0h, b1h);
        }
    }

    // ---- softmax row stats (rows r1, r1+8), e stashed into Lh ----
    float mx1 = -3.4e38f, mx2 = -3.4e38f;
    #pragma unroll
    for (int n = 0; n < 16; n++) {
        mx1 = fmaxf(mx1, fmaxf(acc[n][0], acc[n][1]));
        mx2 = fmaxf(mx2, fmaxf(acc[n][2], acc[n][3]));
    }
    mx1 = fmaxf(mx1, __shfl_xor_sync(0xffffffffu, mx1, 1));
    mx1 = fmaxf(mx1, __shfl_xor_sync(0xffffffffu, mx1, 2));
    mx2 = fmaxf(mx2, __shfl_xor_sync(0xffffffffu, mx2, 1));
    mx2 = fmaxf(mx2, __shfl_xor_sync(0xffffffffu, mx2, 2));

    float s1 = 0.f, s2 = 0.f;
    #pragma unroll
    for (int n = 0; n < 16; n++) {
        int col = 8 * n + 2 * tg;
        float e0 = __expf(acc[n][0] - mx1), e1 = __expf(acc[n][1] - mx1);
        float e2 = __expf(acc[n][2] - mx2), e3 = __expf(acc[n][3] - mx2);
        s1 += e0 + e1; s2 += e2 + e3;
        *(float2*)(Lh + g * LS + col)       = make_float2(e0, e1);
        *(float2*)(Lh + (g + 8) * LS + col) = make_float2(e2, e3);
    }
    s1 += __shfl_xor_sync(0xffffffffu, s1, 1);
    s1 += __shfl_xor_sync(0xffffffffu, s1, 2);
    s2 += __shfl_xor_sync(0xffffffffu, s2, 1);
    s2 += __shfl_xor_sync(0xffffffffu, s2, 2);
    const float i1 = 1.f / s1, i2 = 1.f / s2;
    const float m1 = mu[r1], m2 = mu[r1 + 8];

    // ---- epilogue A: Sc/cov to gmem, L hi/lo to per-warp smem ----
    {
        const size_t ob = (size_t)bm << 14;
        #pragma unroll
        for (int n = 0; n < 16; n++) {
            int col = 8 * n + 2 * tg;
            float2 eA = *(float2*)(Lh + g * LS + col);
            float2 eB = *(float2*)(Lh + (g + 8) * LS + col);
            float mc0 = mu[col], mc1 = mu[col + 1];
            float sc0 = eA.x * i1, sc1 = eA.y * i1;
            float sc2 = eB.x * i2, sc3 = eB.y * i2;
            float cv0 = acc[n][0] * (1.f / 49.f) - m1 * mc0;
            float cv1 = acc[n][1] * (1.f / 49.f) - m1 * mc1;
            float cv2 = acc[n][2] * (1.f / 49.f) - m2 * mc0;
            float cv3 = acc[n][3] * (1.f / 49.f) - m2 * mc1;
            *(float2*)(Sc  + ob + (size_t)r1 * 128 + col)       = make_float2(sc0, sc1);
            *(float2*)(Sc  + ob + (size_t)(r1 + 8) * 128 + col) = make_float2(sc2, sc3);
            *(float2*)(cov + ob + (size_t)r1 * 128 + col)       = make_float2(cv0, cv1);
            *(float2*)(cov + ob + (size_t)(r1 + 8) * 128 + col) = make_float2(cv2, cv3);
            float L0 = fmaf(ALPHA, cv0, sc0), L1 = fmaf(ALPHA, cv1, sc1);
            float L2 = fmaf(ALPHA, cv2, sc2), L3 = fmaf(ALPHA, cv3, sc3);
            float h0 = tf32_hi(L0), h1 = tf32_hi(L1), h2 = tf32_hi(L2), h3 = tf32_hi(L3);
            *(float2*)(Lh + g * LS + col)       = make_float2(h0, h1);
            *(float2*)(Lh + (g + 8) * LS + col) = make_float2(h2, h3);
            *(float2*)(Ll + g * LS + col)       = make_float2(tf32_hi(L0 - h0), tf32_hi(L1 - h1));
            *(float2*)(Ll + (g + 8) * LS + col) = make_float2(tf32_hi(L2 - h2), tf32_hi(L3 - h3));
        }
    }
    __syncwarp();

    // ---- GEMM2: Ec = L * F  (warp strip 16 rows x 56 cols), split tf32 ----
    float acc2[7][4];
    #pragma unroll
    for (int n = 0; n < 7; n++)
        #pragma unroll
        for (int j = 0; j < 4; j++) acc2[n][j] = 0.f;

    const uint32_t* LhU = (const uint32_t*)Lh;
    const uint32_t* LlU = (const uint32_t*)Ll;

    #pragma unroll 1
    for (int kk = 0; kk < 16; kk++) {
        const int ko = 8 * kk + tg;      // d index
        uint32_t a0h = LhU[g * LS + ko],       a1h = LhU[(g + 8) * LS + ko];
        uint32_t a2h = LhU[g * LS + ko + 4],   a3h = LhU[(g + 8) * LS + ko + 4];
        uint32_t a0l = LlU[g * LS + ko],       a1l = LlU[(g + 8) * LS + ko];
        uint32_t a2l = LlU[g * LS + ko + 4],   a3l = LlU[(g + 8) * LS + ko + 4];
        #pragma unroll
        for (int n = 0; n < 7; n++) {
            const int bc = 8 * n + g;    // p index
            uint32_t b0h = FhU[ko * FS + bc], b1h = FhU[(ko + 4) * FS + bc];
            uint32_t b0l = FlU[ko * FS + bc], b1l = FlU[(ko + 4) * FS + bc];
            mma8(acc2[n], a0h, a1h, a2h, a3h, b0h, b1h);
            mma8(acc2[n], a0h, a1h, a2h, a3h, b0l, b1l);
            mma8(acc2[n], a0l, a1l, a2l, a3l, b0h, b1h);
        }
    }

    // ---- epilogue B: fold Ec, out = x * (beta*Ec + x) ----
    {
        const float beta0 = beta[0];
        #pragma unroll
        for (int n = 0; n < 7; n++) {
            const int p0 = 8 * n + 2 * tg;
            #pragma unroll
            for (int e = 0; e < 4; e++) {
                int p = p0 + (e & 1);
                int c = (e < 2) ? r1 : (r1 + 8);
                if (p < PP) {
                    float xv = Fh[c * FS + p] + Fl[c * FS + p];
                    float ec = acc2[n][e];
                    int i = p / PHW, j = p - i * PHW;
                    size_t ga = xoff + (size_t)c * (HW * HW) + i * HW + j;
                    ecmap[ga] = ec;
                    out[ga]   = xv * fmaf(beta0, ec, xv);
                }
            }
        }
    }
}

extern "C" void kernel_launch(void* const* d_in, const int* in_sizes, int n_in,
                              void* d_out, int out_size)
{
    const float* x    = (const float*)d_in[0];
    const float* beta = (const float*)d_in[1];

    float* out   = (float*)d_out;
    float* Sc    = out + N_OUT;
    float* cov   = Sc + N_SCC;
    float* ecmap = cov + N_SCC;

    const int smem_bytes = SMEM_FLOATS * (int)sizeof(float);   // 197120
    cudaFuncSetAttribute(bdca_mma_kernel, cudaFuncAttributeMaxDynamicSharedMemorySize, smem_bytes);
    bdca_mma_kernel<<<BB * 1024, 256, smem_bytes>>>(x, beta, out, Sc, cov, ecmap);
}

// round 10
// speedup vs baseline: 1.3404x; 1.3404x over previous
#include <cuda_runtime.h>
#include <cstdint>

#define BB   4
#define CC   128
#define HW   224
#define PHW  7
#define PP   49
#define ALPHA 0.5f

#define N_OUT 25690112ull
#define N_SCC 67108864ull

// smem layout (floats). F fp32 [128][FS], per-warp L fp32 strips [16][LS], mu[128]
#define FS      56
#define LS      132
#define L_OFF   7168        // 128*56
#define L_WARP  2112        // 16*132
#define MU_OFF  24064       // 7168 + 8*2112
#define SMEM_FLOATS 24192   // 96768 bytes

__device__ __forceinline__ float tf32_hi(float x) {
    uint32_t r; asm("cvt.rna.tf32.f32 %0, %1;" : "=r"(r) : "f"(x));
    return __uint_as_float(r);
}
__device__ __forceinline__ void split_tf32(float f, uint32_t& h, uint32_t& lo) {
    float hf = tf32_hi(f);
    h  = __float_as_uint(hf);
    lo = __float_as_uint(tf32_hi(f - hf));
}
__device__ __forceinline__ void mma8(float* c,
                                     uint32_t a0, uint32_t a1, uint32_t a2, uint32_t a3,
                                     uint32_t b0, uint32_t b1) {
    asm volatile("mma.sync.aligned.m16n8k8.row.col.f32.tf32.tf32.f32 "
        "{%0,%1,%2,%3}, {%4,%5,%6,%7}, {%8,%9}, {%0,%1,%2,%3};"
        : "+f"(c[0]), "+f"(c[1]), "+f"(c[2]), "+f"(c[3])
        : "r"(a0), "r"(a1), "r"(a2), "r"(a3), "r"(b0), "r"(b1));
}

__global__ __launch_bounds__(256, 2)
void bdca_mma_kernel(const float* __restrict__ x, const float* __restrict__ beta,
                     float* __restrict__ out, float* __restrict__ Sc,
                     float* __restrict__ cov, float* __restrict__ ecmap)
{
    extern __shared__ float sm[];
    float* F  = sm;
    float* mu = sm + MU_OFF;

    const int tid = threadIdx.x;
    const int w = tid >> 5, l = tid & 31;
    const int g = l >> 2, tg = l & 3;
    float* Lw = sm + L_OFF + w * L_WARP;

    const int bm = blockIdx.x;
    const int b  = bm >> 10, m = bm & 1023;
    const int hh = m >> 5, ww = m & 31;
    const size_t xoff = (size_t)b * (CC * HW * HW) + (size_t)(hh * PHW) * HW + (size_t)(ww * PHW);

    // ---- zero F pad cols 49..55, stage F (fp32) ----
    for (int t = tid; t < CC * (FS - PP); t += 256) {
        int c = t / (FS - PP), p = PP + t % (FS - PP);
        F[c * FS + p] = 0.f;
    }
    for (int idx = tid; idx < CC * PP; idx += 256) {
        int c = idx / PP, p = idx - c * PP;
        int i = p / PHW, j = p - i * PHW;
        F[c * FS + p] = __ldg(x + xoff + (size_t)c * (HW * HW) + i * HW + j);
    }
    __syncthreads();

    // ---- mu: warp w owns channels 16w..16w+15 ----
    {
        #pragma unroll 4
        for (int cc = 0; cc < 16; cc++) {
            int c = 16 * w + cc;
            float v = F[c * FS + l];
            if (l < 17) v += F[c * FS + 32 + l];
            #pragma unroll
            for (int o = 16; o; o >>= 1) v += __shfl_xor_sync(0xffffffffu, v, o);
            if (l == 0) mu[c] = v * (1.f / 49.f);
        }
    }
    __syncthreads();

    const int r1 = 16 * w + g;

    // ---- GEMM1: G = F * F^T, warp strip 16 rows x 128 cols, split tf32 ----
    float acc[16][4];
    #pragma unroll
    for (int n = 0; n < 16; n++)
        #pragma unroll
        for (int j = 0; j < 4; j++) acc[n][j] = 0.f;

    #pragma unroll 1
    for (int k = 0; k < 7; k++) {
        const int ko = 8 * k + tg;
        uint32_t a0h, a0l, a1h, a1l, a2h, a2l, a3h, a3l;
        split_tf32(F[r1 * FS + ko],           a0h, a0l);
        split_tf32(F[(r1 + 8) * FS + ko],     a1h, a1l);
        split_tf32(F[r1 * FS + ko + 4],       a2h, a2l);
        split_tf32(F[(r1 + 8) * FS + ko + 4], a3h, a3l);
        #pragma unroll
        for (int n = 0; n < 16; n++) {
            const int br = (8 * n + g) * FS + ko;
            uint32_t b0h, b0l, b1h, b1l;
            split_tf32(F[br],     b0h, b0l);
            split_tf32(F[br + 4], b1h, b1l);
            mma8(acc[n], a0h, a1h, a2h, a3h, b0h, b1h);
            mma8(acc[n], a0h, a1h, a2h, a3h, b0l, b1l);
            mma8(acc[n], a0l, a1l, a2l, a3l, b0h, b1h);
        }
    }

    // ---- softmax row stats (rows r1, r1+8), e stashed into Lw ----
    float mx1 = -3.4e38f, mx2 = -3.4e38f;
    #pragma unroll
    for (int n = 0; n < 16; n++) {
        mx1 = fmaxf(mx1, fmaxf(acc[n][0], acc[n][1]));
        mx2 = fmaxf(mx2, fmaxf(acc[n][2], acc[n][3]));
    }
    mx1 = fmaxf(mx1, __shfl_xor_sync(0xffffffffu, mx1, 1));
    mx1 = fmaxf(mx1, __shfl_xor_sync(0xffffffffu, mx1, 2));
    mx2 = fmaxf(mx2, __shfl_xor_sync(0xffffffffu, mx2, 1));
    mx2 = fmaxf(mx2, __shfl_xor_sync(0xffffffffu, mx2, 2));

    float s1 = 0.f, s2 = 0.f;
    #pragma unroll
    for (int n = 0; n < 16; n++) {
        int col = 8 * n + 2 * tg;
        float e0 = __expf(acc[n][0] - mx1), e1 = __expf(acc[n][1] - mx1);
        float e2 = __expf(acc[n][2] - mx2), e3 = __expf(acc[n][3] - mx2);
        s1 += e0 + e1; s2 += e2 + e3;
        *(float2*)(Lw + g * LS + col)       = make_float2(e0, e1);
        *(float2*)(Lw + (g + 8) * LS + col) = make_float2(e2, e3);
    }
    s1 += __shfl_xor_sync(0xffffffffu, s1, 1);
    s1 += __shfl_xor_sync(0xffffffffu, s1, 2);
    s2 += __shfl_xor_sync(0xffffffffu, s2, 1);
    s2 += __shfl_xor_sync(0xffffffffu, s2, 2);
    const float i1 = 1.f / s1, i2 = 1.f / s2;
    const float m1 = mu[r1], m2 = mu[r1 + 8];

    // ---- epilogue A: Sc/cov to gmem, L (fp32) to per-warp smem strip ----
    {
        const size_t ob = (size_t)bm << 14;
        #pragma unroll
        for (int n = 0; n < 16; n++) {
            int col = 8 * n + 2 * tg;
            float2 eA = *(float2*)(Lw + g * LS + col);
            float2 eB = *(float2*)(Lw + (g + 8) * LS + col);
            float2 mc = *(float2*)(mu + col);
            float sc0 = eA.x * i1, sc1 = eA.y * i1;
            float sc2 = eB.x * i2, sc3 = eB.y * i2;
            float cv0 = acc[n][0] * (1.f / 49.f) - m1 * mc.x;
            float cv1 = acc[n][1] * (1.f / 49.f) - m1 * mc.y;
            float cv2 = acc[n][2] * (1.f / 49.f) - m2 * mc.x;
            float cv3 = acc[n][3] * (1.f / 49.f) - m2 * mc.y;
            *(float2*)(Sc  + ob + (size_t)r1 * 128 + col)       = make_float2(sc0, sc1);
            *(float2*)(Sc  + ob + (size_t)(r1 + 8) * 128 + col) = make_float2(sc2, sc3);
            *(float2*)(cov + ob + (size_t)r1 * 128 + col)       = make_float2(cv0, cv1);
            *(float2*)(cov + ob + (size_t)(r1 + 8) * 128 + col) = make_float2(cv2, cv3);
            *(float2*)(Lw + g * LS + col) =
                make_float2(fmaf(ALPHA, cv0, sc0), fmaf(ALPHA, cv1, sc1));
            *(float2*)(Lw + (g + 8) * LS + col) =
                make_float2(fmaf(ALPHA, cv2, sc2), fmaf(ALPHA, cv3, sc3));
        }
    }
    __syncwarp();

    // ---- GEMM2: Ec = L * F  (warp strip 16 rows x 56 cols), split tf32 ----
    float acc2[7][4];
    #pragma unroll
    for (int n = 0; n < 7; n++)
        #pragma unroll
        for (int j = 0; j < 4; j++) acc2[n][j] = 0.f;

    #pragma unroll 1
    for (int kk = 0; kk < 16; kk++) {
        const int ko = 8 * kk + tg;      // d index
        uint32_t a0h, a0l, a1h, a1l, a2h, a2l, a3h, a3l;
        split_tf32(Lw[g * LS + ko],           a0h, a0l);
        split_tf32(Lw[(g + 8) * LS + ko],     a1h, a1l);
        split_tf32(Lw[g * LS + ko + 4],       a2h, a2l);
        split_tf32(Lw[(g + 8) * LS + ko + 4], a3h, a3l);
        #pragma unroll
        for (int n = 0; n < 7; n++) {
            const int bc = 8 * n + g;    // p index
            uint32_t b0h, b0l, b1h, b1l;
            split_tf32(F[ko * FS + bc],       b0h, b0l);
            split_tf32(F[(ko + 4) * FS + bc], b1h, b1l);
            mma8(acc2[n], a0h, a1h, a2h, a3h, b0h, b1h);
            mma8(acc2[n], a0h, a1h, a2h, a3h, b0l, b1l);
            mma8(acc2[n], a0l, a1l, a2l, a3l, b0h, b1h);
        }
    }

    // ---- epilogue B: fold Ec, out = x * (beta*Ec + x) ----
    {
        const float beta0 = beta[0];
        #pragma unroll
        for (int n = 0; n < 7; n++) {
            const int p0 = 8 * n + 2 * tg;
            #pragma unroll
            for (int e = 0; e < 4; e++) {
                int p = p0 + (e & 1);
                int c = (e < 2) ? r1 : (r1 + 8);
                if (p < PP) {
                    float xv = F[c * FS + p];
                    float ec = acc2[n][e];
                    int i = p / PHW, j = p - i * PHW;
                    size_t ga = xoff + (size_t)c * (HW * HW) + i * HW + j;
                    ecmap[ga] = ec;
                    out[ga]   = xv * fmaf(beta0, ec, xv);
                }
            }
        }
    }
}

extern "C" void kernel_launch(void* const* d_in, const int* in_sizes, int n_in,
                              void* d_out, int out_size)
{
    const float* x    = (const float*)d_in[0];
    const float* beta = (const float*)d_in[1];

    float* out   = (float*)d_out;
    float* Sc    = out + N_OUT;
    float* cov   = Sc + N_SCC;
    float* ecmap = cov + N_SCC;

    const int smem_bytes = SMEM_FLOATS * (int)sizeof(float);   // 96768
    cudaFuncSetAttribute(bdca_mma_kernel, cudaFuncAttributeMaxDynamicSharedMemorySize, smem_bytes);
    bdca_mma_kernel<<<BB * 1024, 256, smem_bytes>>>(x, beta, out, Sc, cov, ecmap);
}

// round 12
// speedup vs baseline: 1.4036x; 1.0472x over previous
#include <cuda_runtime.h>
#include <cstdint>

#define BB   4
#define CC   128
#define HW   224
#define PHW  7
#define PP   49
#define ALPHA 0.5f

#define N_OUT 25690112ull
#define N_SCC 67108864ull

// smem: F packed (hi,lo) float2 [128][FS2], mu[128]
#define FS2     68          // float2 stride
#define MU_OFF  17408       // 128*68*2 floats
#define SMEM_FLOATS 17536   // 70144 bytes

__device__ __forceinline__ float tf32_hi(float x) {
    uint32_t r; asm("cvt.rna.tf32.f32 %0, %1;" : "=r"(r) : "f"(x));
    return __uint_as_float(r);
}
__device__ __forceinline__ void split_tf32(float f, uint32_t& h, uint32_t& lo) {
    float hf = tf32_hi(f);
    h  = __float_as_uint(hf);
    lo = __float_as_uint(tf32_hi(f - hf));
}
__device__ __forceinline__ void mma8(float* c,
                                     uint32_t a0, uint32_t a1, uint32_t a2, uint32_t a3,
                                     uint32_t b0, uint32_t b1) {
    asm volatile("mma.sync.aligned.m16n8k8.row.col.f32.tf32.tf32.f32 "
        "{%0,%1,%2,%3}, {%4,%5,%6,%7}, {%8,%9}, {%0,%1,%2,%3};"
        : "+f"(c[0]), "+f"(c[1]), "+f"(c[2]), "+f"(c[3])
        : "r"(a0), "r"(a1), "r"(a2), "r"(a3), "r"(b0), "r"(b1));
}

__global__ __launch_bounds__(256, 2)
void bdca_mma_kernel(const float* __restrict__ x, const float* __restrict__ beta,
                     float* __restrict__ out, float* __restrict__ Sc,
                     float* __restrict__ cov, float* __restrict__ ecmap)
{
    extern __shared__ float sm[];
    float2* F2 = (float2*)sm;          // [128][FS2] packed (hi, lo)
    float*  mu = sm + MU_OFF;

    const int tid = threadIdx.x;
    const int w = tid >> 5, l = tid & 31;
    const int g = l >> 2, tg = l & 3;

    const int bm = blockIdx.x;
    const int b  = bm >> 10, m = bm & 1023;
    const int hh = m >> 5, ww = m & 31;
    const size_t xoff = (size_t)b * (CC * HW * HW) + (size_t)(hh * PHW) * HW + (size_t)(ww * PHW);

    // ---- zero pad pixels 49..55, stage F as (hi,lo) pairs ----
    for (int t = tid; t < CC * 7; t += 256) {
        int c = t / 7, p = PP + t % 7;
        F2[c * FS2 + p] = make_float2(0.f, 0.f);
    }
    for (int idx = tid; idx < CC * PP; idx += 256) {
        int c = idx / PP, p = idx - c * PP;
        int i = p / PHW, j = p - i * PHW;
        float xv = __ldg(x + xoff + (size_t)c * (HW * HW) + i * HW + j);
        float hi = tf32_hi(xv);
        F2[c * FS2 + p] = make_float2(hi, tf32_hi(xv - hi));
    }
    __syncthreads();

    // ---- mu: warp w owns channels 16w..16w+15 ----
    {
        #pragma unroll 4
        for (int cc = 0; cc < 16; cc++) {
            int c = 16 * w + cc;
            float2 v2 = F2[c * FS2 + l];
            float v = v2.x + v2.y;
            if (l < 17) {
                float2 u2 = F2[c * FS2 + 32 + l];
                v += u2.x + u2.y;
            }
            #pragma unroll
            for (int o = 16; o; o >>= 1) v += __shfl_xor_sync(0xffffffffu, v, o);
            if (l == 0) mu[c] = v * (1.f / 49.f);
        }
    }
    __syncthreads();

    const int r1 = 16 * w + g;

    // ---- GEMM1: G = F * F^T, warp strip 16 rows x 128 cols, split tf32 ----
    float acc[16][4];
    #pragma unroll
    for (int n = 0; n < 16; n++)
        #pragma unroll
        for (int j = 0; j < 4; j++) acc[n][j] = 0.f;

    #pragma unroll 1
    for (int k = 0; k < 7; k++) {
        const int ko = 8 * k + tg;
        float2 A0 = F2[r1 * FS2 + ko];
        float2 A1 = F2[(r1 + 8) * FS2 + ko];
        float2 A2 = F2[r1 * FS2 + ko + 4];
        float2 A3 = F2[(r1 + 8) * FS2 + ko + 4];
        uint32_t a0h = __float_as_uint(A0.x), a0l = __float_as_uint(A0.y);
        uint32_t a1h = __float_as_uint(A1.x), a1l = __float_as_uint(A1.y);
        uint32_t a2h = __float_as_uint(A2.x), a2l = __float_as_uint(A2.y);
        uint32_t a3h = __float_as_uint(A3.x), a3l = __float_as_uint(A3.y);
        #pragma unroll
        for (int n = 0; n < 16; n++) {
            const int br = (8 * n + g) * FS2 + ko;
            float2 B0 = F2[br];
            float2 B1 = F2[br + 4];
            uint32_t b0h = __float_as_uint(B0.x), b0l = __float_as_uint(B0.y);
            uint32_t b1h = __float_as_uint(B1.x), b1l = __float_as_uint(B1.y);
            mma8(acc[n], a0h, a1h, a2h, a3h, b0h, b1h);
            mma8(acc[n], a0h, a1h, a2h, a3h, b0l, b1l);
            mma8(acc[n], a0l, a1l, a2l, a3l, b0h, b1h);
        }
    }

    // ---- softmax row stats (rows r1, r1+8) ----
    float mx1 = -3.4e38f, mx2 = -3.4e38f;
    #pragma unroll
    for (int n = 0; n < 16; n++) {
        mx1 = fmaxf(mx1, fmaxf(acc[n][0], acc[n][1]));
        mx2 = fmaxf(mx2, fmaxf(acc[n][2], acc[n][3]));
    }
    mx1 = fmaxf(mx1, __shfl_xor_sync(0xffffffffu, mx1, 1));
    mx1 = fmaxf(mx1, __shfl_xor_sync(0xffffffffu, mx1, 2));
    mx2 = fmaxf(mx2, __shfl_xor_sync(0xffffffffu, mx2, 1));
    mx2 = fmaxf(mx2, __shfl_xor_sync(0xffffffffu, mx2, 2));

    float s1 = 0.f, s2 = 0.f;
    #pragma unroll
    for (int n = 0; n < 16; n++) {
        s1 += __expf(acc[n][0] - mx1) + __expf(acc[n][1] - mx1);
        s2 += __expf(acc[n][2] - mx2) + __expf(acc[n][3] - mx2);
    }
    s1 += __shfl_xor_sync(0xffffffffu, s1, 1);
    s1 += __shfl_xor_sync(0xffffffffu, s1, 2);
    s2 += __shfl_xor_sync(0xffffffffu, s2, 1);
    s2 += __shfl_xor_sync(0xffffffffu, s2, 2);
    const float i1 = 1.f / s1, i2 = 1.f / s2;
    const float m1 = mu[r1], m2 = mu[r1 + 8];

    // ---- epilogue A: Sc/cov to gmem; L replaces G in acc (C-fragment layout) ----
    {
        const size_t ob = (size_t)bm << 14;
        #pragma unroll
        for (int n = 0; n < 16; n++) {
            int col = 8 * n + 2 * tg;
            float2 mc = *(float2*)(mu + col);
            float sc0 = __expf(acc[n][0] - mx1) * i1;
            float sc1 = __expf(acc[n][1] - mx1) * i1;
            float sc2 = __expf(acc[n][2] - mx2) * i2;
            float sc3 = __expf(acc[n][3] - mx2) * i2;
            float cv0 = acc[n][0] * (1.f / 49.f) - m1 * mc.x;
            float cv1 = acc[n][1] * (1.f / 49.f) - m1 * mc.y;
            float cv2 = acc[n][2] * (1.f / 49.f) - m2 * mc.x;
            float cv3 = acc[n][3] * (1.f / 49.f) - m2 * mc.y;
            *(float2*)(Sc  + ob + (size_t)r1 * 128 + col)       = make_float2(sc0, sc1);
            *(float2*)(Sc  + ob + (size_t)(r1 + 8) * 128 + col) = make_float2(sc2, sc3);
            *(float2*)(cov + ob + (size_t)r1 * 128 + col)       = make_float2(cv0, cv1);
            *(float2*)(cov + ob + (size_t)(r1 + 8) * 128 + col) = make_float2(cv2, cv3);
            acc[n][0] = fmaf(ALPHA, cv0, sc0);
            acc[n][1] = fmaf(ALPHA, cv1, sc1);
            acc[n][2] = fmaf(ALPHA, cv2, sc2);
            acc[n][3] = fmaf(ALPHA, cv3, sc3);
        }
    }

    // ---- GEMM2: Ec = L * F. A fragments built from acc via quad shuffles ----
    float acc2[7][4];
    #pragma unroll
    for (int n = 0; n < 7; n++)
        #pragma unroll
        for (int j = 0; j < 4; j++) acc2[n][j] = 0.f;

    const int s0 = (l & 28) | (tg >> 1);
    const bool odd = (tg & 1);

    #pragma unroll
    for (int kk = 0; kk < 16; kk++) {
        // A block = L[rows r1,r1+8][cols 8kk..8kk+7]; convert C-layout -> A-layout
        float v00 = __shfl_sync(0xffffffffu, acc[kk][0], s0);
        float v01 = __shfl_sync(0xffffffffu, acc[kk][1], s0);
        float v10 = __shfl_sync(0xffffffffu, acc[kk][2], s0);
        float v11 = __shfl_sync(0xffffffffu, acc[kk][3], s0);
        float v20 = __shfl_sync(0xffffffffu, acc[kk][0], s0 + 2);
        float v21 = __shfl_sync(0xffffffffu, acc[kk][1], s0 + 2);
        float v30 = __shfl_sync(0xffffffffu, acc[kk][2], s0 + 2);
        float v31 = __shfl_sync(0xffffffffu, acc[kk][3], s0 + 2);
        float a0f = odd ? v01 : v00;   // L[r1][8kk+tg]
        float a1f = odd ? v11 : v10;   // L[r1+8][8kk+tg]
        float a2f = odd ? v21 : v20;   // L[r1][8kk+tg+4]
        float a3f = odd ? v31 : v30;   // L[r1+8][8kk+tg+4]
        uint32_t a0h, a0l, a1h, a1l, a2h, a2l, a3h, a3l;
        split_tf32(a0f, a0h, a0l);
        split_tf32(a1f, a1h, a1l);
        split_tf32(a2f, a2h, a2l);
        split_tf32(a3f, a3h, a3l);
        const int ko = 8 * kk + tg;    // d index (reduction)
        #pragma unroll
        for (int n = 0; n < 7; n++) {
            const int bc = 8 * n + g;  // p index
            float2 B0 = F2[ko * FS2 + bc];
            float2 B1 = F2[(ko + 4) * FS2 + bc];
            uint32_t b0h = __float_as_uint(B0.x), b0l = __float_as_uint(B0.y);
            uint32_t b1h = __float_as_uint(B1.x), b1l = __float_as_uint(B1.y);
            mma8(acc2[n], a0h, a1h, a2h, a3h, b0h, b1h);
            mma8(acc2[n], a0h, a1h, a2h, a3h, b0l, b1l);
            mma8(acc2[n], a0l, a1l, a2l, a3l, b0h, b1h);
        }
    }

    // ---- epilogue B: fold Ec, out = x * (beta*Ec + x) ----
    {
        const float beta0 = beta[0];
        #pragma unroll
        for (int n = 0; n < 7; n++) {
            const int p0 = 8 * n + 2 * tg;
            #pragma unroll
            for (int e = 0; e < 4; e++) {
                int p = p0 + (e & 1);
                int c = (e < 2) ? r1 : (r1 + 8);
                if (p < PP) {
                    float2 xv2 = F2[c * FS2 + p];
                    float xv = xv2.x + xv2.y;
                    float ec = acc2[n][e];
                    int i = p / PHW, j = p - i * PHW;
                    size_t ga = xoff + (size_t)c * (HW * HW) + i * HW + j;
                    ecmap[ga] = ec;
                    out[ga]   = xv * fmaf(beta0, ec, xv);
                }
            }
        }
    }
}

extern "C" void kernel_launch(void* const* d_in, const int* in_sizes, int n_in,
                              void* d_out, int out_size)
{
    const float* x    = (const float*)d_in[0];
    const float* beta = (const float*)d_in[1];

    float* out   = (float*)d_out;
    float* Sc    = out + N_OUT;
    float* cov   = Sc + N_SCC;
    float* ecmap = cov + N_SCC;

    const int smem_bytes = SMEM_FLOATS * (int)sizeof(float);   // 70144
    cudaFuncSetAttribute(bdca_mma_kernel, cudaFuncAttributeMaxDynamicSharedMemorySize, smem_bytes);
    bdca_mma_kernel<<<BB * 1024, 256, smem_bytes>>>(x, beta, out, Sc, cov, ecmap);
}